// round 11
// baseline (speedup 1.0000x reference)
#include <cuda_runtime.h>
#include <cuda_bf16.h>
#include <cuda_fp16.h>
#include <math_constants.h>

#define NN 50000
#define EE 800000
#define INF_DIM 128
#define HH 8
#define FF 32
#define OUTD 256   // HH*FF
#define CC 2

#define SCAN_B 256
#define NBLK ((NN + SCAN_B - 1) / SCAN_B)   // 196

// -------- scratch (static __device__ globals; allocation-free) --------
__device__ __half d_zh[NN * OUTD];     // fp16 projected features (gather payload)
__device__ float  d_el[NN * HH];
__device__ float  d_er[NN * HH];
__device__ int    d_cnt[NN];
__device__ int    d_rowptr[NN + 1];
__device__ int    d_wp[NN];
__device__ int    d_esrc[EE];
__device__ int    d_bsum[NBLK];
__device__ int    d_bars[3];           // grid-barrier counters (self-resetting)
__device__ float  d_z2[NN * CC];
__device__ float  d_el2[NN];
__device__ float  d_er2[NN];

// ====================== GEMM1 (tf32 MMA) + fused el/er epilogue ======================
#define GBM 128
#define GBN 64
#define KC 32

__device__ __forceinline__ unsigned f2tf32(float x) {
    unsigned u;
    asm("cvt.rna.tf32.f32 %0, %1;" : "=r"(u) : "f"(x));
    return u;
}

__global__ __launch_bounds__(256) void gemm1_mma_kernel(const float* __restrict__ A,
                                                        const float* __restrict__ B,
                                                        const float* __restrict__ al,
                                                        const float* __restrict__ ar) {
    __shared__ float As[GBM][KC + 4];
    __shared__ float Bs[KC][72];

    const int bm = blockIdx.x * GBM;
    const int bn = blockIdx.y * GBN;
    const int tid = threadIdx.x;
    const int wid = tid >> 5;
    const int l = tid & 31;
    const int wm = wid & 3;
    const int wn = wid >> 2;

    if (blockIdx.y == 0) {
        int gt = blockIdx.x * 256 + tid;
        if (gt < NN) d_cnt[gt] = 0;
    }

    float c[2][4][4];
#pragma unroll
    for (int mt = 0; mt < 2; mt++)
#pragma unroll
        for (int nt = 0; nt < 4; nt++)
#pragma unroll
            for (int r = 0; r < 4; r++) c[mt][nt][r] = 0.f;

    for (int kc = 0; kc < INF_DIM; kc += KC) {
#pragma unroll
        for (int i = 0; i < 4; i++) {
            int row = (tid >> 3) + i * 32;
            int col = (tid & 7) * 4;
            int grow = bm + row;
            float4 v = make_float4(0.f, 0.f, 0.f, 0.f);
            if (grow < NN) v = *(const float4*)(A + (size_t)grow * INF_DIM + kc + col);
            As[row][col + 0] = __uint_as_float(f2tf32(v.x));
            As[row][col + 1] = __uint_as_float(f2tf32(v.y));
            As[row][col + 2] = __uint_as_float(f2tf32(v.z));
            As[row][col + 3] = __uint_as_float(f2tf32(v.w));
        }
#pragma unroll
        for (int i = 0; i < 2; i++) {
            int k = (tid >> 4) + i * 16;
            int n = (tid & 15) * 4;
            float4 v = *(const float4*)(B + (size_t)(kc + k) * OUTD + bn + n);
            Bs[k][n + 0] = __uint_as_float(f2tf32(v.x));
            Bs[k][n + 1] = __uint_as_float(f2tf32(v.y));
            Bs[k][n + 2] = __uint_as_float(f2tf32(v.z));
            Bs[k][n + 3] = __uint_as_float(f2tf32(v.w));
        }
        __syncthreads();

        const int fr = l >> 2;
        const int fc = l & 3;
#pragma unroll
        for (int ks = 0; ks < KC; ks += 8) {
            unsigned a[2][4], b[4][2];
#pragma unroll
            for (int mt = 0; mt < 2; mt++) {
                int base = wm * 32 + mt * 16;
                a[mt][0] = __float_as_uint(As[base + fr][ks + fc]);
                a[mt][1] = __float_as_uint(As[base + fr + 8][ks + fc]);
                a[mt][2] = __float_as_uint(As[base + fr][ks + fc + 4]);
                a[mt][3] = __float_as_uint(As[base + fr + 8][ks + fc + 4]);
            }
#pragma unroll
            for (int nt = 0; nt < 4; nt++) {
                int coln = wn * 32 + nt * 8 + fr;
                b[nt][0] = __float_as_uint(Bs[ks + fc][coln]);
                b[nt][1] = __float_as_uint(Bs[ks + fc + 4][coln]);
            }
#pragma unroll
            for (int mt = 0; mt < 2; mt++)
#pragma unroll
                for (int nt = 0; nt < 4; nt++) {
                    asm volatile(
                        "mma.sync.aligned.m16n8k8.row.col.f32.tf32.tf32.f32 "
                        "{%0,%1,%2,%3}, {%4,%5,%6,%7}, {%8,%9}, {%0,%1,%2,%3};\n"
                        : "+f"(c[mt][nt][0]), "+f"(c[mt][nt][1]),
                          "+f"(c[mt][nt][2]), "+f"(c[mt][nt][3])
                        : "r"(a[mt][0]), "r"(a[mt][1]), "r"(a[mt][2]), "r"(a[mt][3]),
                          "r"(b[nt][0]), "r"(b[nt][1]));
                }
        }
        __syncthreads();
    }

    const int h = blockIdx.y * 2 + wn;
    const int fr = l >> 2;
    const int fc = l & 3;

    float alv[4][2], arv[4][2];
#pragma unroll
    for (int nt = 0; nt < 4; nt++) {
        int cih = nt * 8 + fc * 2;
        alv[nt][0] = al[h * FF + cih];
        alv[nt][1] = al[h * FF + cih + 1];
        arv[nt][0] = ar[h * FF + cih];
        arv[nt][1] = ar[h * FF + cih + 1];
    }

    float pel[2][2] = {{0.f, 0.f}, {0.f, 0.f}};
    float per[2][2] = {{0.f, 0.f}, {0.f, 0.f}};

#pragma unroll
    for (int mt = 0; mt < 2; mt++) {
        int r0 = bm + wm * 32 + mt * 16 + fr;
        int r1 = r0 + 8;
#pragma unroll
        for (int nt = 0; nt < 4; nt++) {
            float z00 = c[mt][nt][0], z01 = c[mt][nt][1];
            float z10 = c[mt][nt][2], z11 = c[mt][nt][3];
            pel[mt][0] += z00 * alv[nt][0] + z01 * alv[nt][1];
            pel[mt][1] += z10 * alv[nt][0] + z11 * alv[nt][1];
            per[mt][0] += z00 * arv[nt][0] + z01 * arv[nt][1];
            per[mt][1] += z10 * arv[nt][0] + z11 * arv[nt][1];
            int colg = bn + wn * 32 + nt * 8 + fc * 2;
            if (r0 < NN) *(__half2*)(d_zh + (size_t)r0 * OUTD + colg) = __floats2half2_rn(z00, z01);
            if (r1 < NN) *(__half2*)(d_zh + (size_t)r1 * OUTD + colg) = __floats2half2_rn(z10, z11);
        }
    }
#pragma unroll
    for (int o = 1; o < 4; o <<= 1) {
#pragma unroll
        for (int mt = 0; mt < 2; mt++) {
#pragma unroll
            for (int i = 0; i < 2; i++) {
                pel[mt][i] += __shfl_xor_sync(0xffffffffu, pel[mt][i], o);
                per[mt][i] += __shfl_xor_sync(0xffffffffu, per[mt][i], o);
            }
        }
    }
    if (fc == 0) {
#pragma unroll
        for (int mt = 0; mt < 2; mt++) {
#pragma unroll
            for (int i = 0; i < 2; i++) {
                int row = bm + wm * 32 + mt * 16 + fr + i * 8;
                if (row < NN) {
                    d_el[row * HH + h] = pel[mt][i];
                    d_er[row * HH + h] = per[mt][i];
                }
            }
        }
    }
}

// ====================== fused CSR build: hist + scan + fill, one kernel ======================
// Exactly NBLK=196 blocks x 256 threads: co-residency guaranteed (196 < 148 SMs x >=2),
// so software grid barriers are safe. Counters self-reset: barrier i's last arriver
// resets counter (i+2)%3, so each counter is 0 again before its next use (graph replays).
__device__ __forceinline__ int warp_incl_scan(int v, int l) {
#pragma unroll
    for (int o = 1; o < 32; o <<= 1) {
        int u = __shfl_up_sync(0xffffffffu, v, o);
        if (l >= o) v += u;
    }
    return v;
}

__device__ __forceinline__ void grid_barrier(int idx) {
    __syncthreads();
    if (threadIdx.x == 0) {
        __threadfence();
        int ticket = atomicAdd(&d_bars[idx], 1);
        if (ticket == NBLK - 1) {
            atomicExch(&d_bars[(idx + 2) % 3], 0);   // recycle for next replay
        }
        while (atomicAdd(&d_bars[idx], 0) < NBLK) {}
        __threadfence();
    }
    __syncthreads();
}

__global__ __launch_bounds__(SCAN_B) void csr_build_kernel(const int* __restrict__ src,
                                                           const int* __restrict__ dst) {
    const int t = threadIdx.x;
    const int gthreads = NBLK * SCAN_B;     // 50176
    const int gtid = blockIdx.x * SCAN_B + t;

    // --- phase A: histogram (d_cnt zeroed by gemm1, which precedes in-stream) ---
    for (int e = gtid; e < EE; e += gthreads)
        atomicAdd(&d_cnt[dst[e]], 1);

    grid_barrier(0);

    // --- phase B1: block-local exclusive scan of 256 counts + block total ---
    __shared__ int wsum[SCAN_B / 32];
    {
        int l = t & 31;
        int wid = t >> 5;
        int v = (gtid < NN) ? d_cnt[gtid] : 0;
        int inc = warp_incl_scan(v, l);
        if (l == 31) wsum[wid] = inc;
        __syncthreads();
        if (wid == 0) {
            int wv = (l < SCAN_B / 32) ? wsum[l] : 0;
            wv = warp_incl_scan(wv, l);
            if (l < SCAN_B / 32) wsum[l] = wv;
        }
        __syncthreads();
        int base = (wid == 0) ? 0 : wsum[wid - 1];
        int excl = base + inc - v;
        if (gtid < NN) d_rowptr[gtid] = excl;
        if (t == SCAN_B - 1) d_bsum[blockIdx.x] = base + inc;
    }

    grid_barrier(1);

    // --- phase B2: lookback sum of preceding block totals, apply ---
    {
        __shared__ int wred[SCAN_B / 32];
        __shared__ int soff;
        int l = t & 31;
        int wid = t >> 5;
        int v = (t < blockIdx.x) ? d_bsum[t] : 0;   // NBLK=196 < 256
#pragma unroll
        for (int o = 16; o > 0; o >>= 1) v += __shfl_xor_sync(0xffffffffu, v, o);
        if (l == 0) wred[wid] = v;
        __syncthreads();
        if (t == 0) {
            int acc = 0;
#pragma unroll
            for (int i = 0; i < SCAN_B / 32; i++) acc += wred[i];
            soff = acc;
        }
        __syncthreads();
        if (gtid < NN) {
            int r = d_rowptr[gtid] + soff;
            d_rowptr[gtid] = r;
            d_wp[gtid] = r;
        }
        if (gtid == 0) d_rowptr[NN] = EE;
    }

    grid_barrier(2);

    // --- phase C: fill edge lists ---
    for (int e = gtid; e < EE; e += gthreads) {
        int d = dst[e];
        int pos = atomicAdd(&d_wp[d], 1);
        d_esrc[pos] = src[e];
    }
}

__device__ __forceinline__ float elu_f(float x) { return x > 0.f ? x : expm1f(x); }

// ====================== K7: layer-1 aggregation + fused layer-2 projection ======================
// Plain-exp softmax (shift-invariance: max-subtraction unnecessary, logits bounded ~|15|).
// warp per dst node; lane l -> features l*8..l*8+7, head = l/4.
__global__ __launch_bounds__(256) void agg1_kernel(const float* __restrict__ b1,
                                                   const float* __restrict__ W2,
                                                   const float* __restrict__ al2,
                                                   const float* __restrict__ ar2) {
    int w = blockIdx.x * 8 + (threadIdx.x >> 5);
    if (w >= NN) return;
    int l = threadIdx.x & 31;
    int hh = l >> 2;
    int beg = d_rowptr[w], end = d_rowptr[w + 1];

    float o[8];
    const float* bb = b1 + l * 8;

    if (beg == end) {
#pragma unroll
        for (int i = 0; i < 8; i++) o[i] = elu_f(bb[i]);
    } else {
        float er_h = d_er[w * HH + hh];
        float s = 0.f;
        float acc[8];
#pragma unroll
        for (int i = 0; i < 8; i++) acc[i] = 0.f;

#pragma unroll 8
        for (int e = beg; e < end; e++) {
            int si = __ldg(&d_esrc[e]);
            float xv = __ldg(&d_el[si * HH + hh]) + er_h;
            xv = xv > 0.f ? xv : 0.2f * xv;
            float ex = __expf(xv);
            s += ex;
            uint4 raw = *(const uint4*)(d_zh + (size_t)si * OUTD + l * 8);
            float2 z0 = __half22float2(*(const __half2*)&raw.x);
            float2 z1 = __half22float2(*(const __half2*)&raw.y);
            float2 z2 = __half22float2(*(const __half2*)&raw.z);
            float2 z3 = __half22float2(*(const __half2*)&raw.w);
            acc[0] = fmaf(ex, z0.x, acc[0]);
            acc[1] = fmaf(ex, z0.y, acc[1]);
            acc[2] = fmaf(ex, z1.x, acc[2]);
            acc[3] = fmaf(ex, z1.y, acc[3]);
            acc[4] = fmaf(ex, z2.x, acc[4]);
            acc[5] = fmaf(ex, z2.y, acc[5]);
            acc[6] = fmaf(ex, z3.x, acc[6]);
            acc[7] = fmaf(ex, z3.y, acc[7]);
        }
        float inv_s = 1.f / s;
#pragma unroll
        for (int i = 0; i < 8; i++) o[i] = elu_f(fmaf(acc[i], inv_s, bb[i]));
    }

    // ---- fused layer-2 projection: z2 = h @ W2, h held across the warp ----
    float pz0, pz1;
    const float4* W2v = (const float4*)(W2 + l * 16);  // 8 cols x 2 = 16 floats per lane
    float4 w0 = W2v[0], w1 = W2v[1], w2 = W2v[2], w3 = W2v[3];
    pz0 = o[0] * w0.x + o[1] * w0.z + o[2] * w1.x + o[3] * w1.z +
          o[4] * w2.x + o[5] * w2.z + o[6] * w3.x + o[7] * w3.z;
    pz1 = o[0] * w0.y + o[1] * w0.w + o[2] * w1.y + o[3] * w1.w +
          o[4] * w2.y + o[5] * w2.w + o[6] * w3.y + o[7] * w3.w;
#pragma unroll
    for (int sh = 16; sh > 0; sh >>= 1) {
        pz0 += __shfl_xor_sync(0xffffffffu, pz0, sh);
        pz1 += __shfl_xor_sync(0xffffffffu, pz1, sh);
    }
    if (l == 0) {
        d_z2[2 * w + 0] = pz0;
        d_z2[2 * w + 1] = pz1;
        d_el2[w] = pz0 * al2[0] + pz1 * al2[1];
        d_er2[w] = pz0 * ar2[0] + pz1 * ar2[1];
    }
}

// ====================== K9: layer-2 aggregation (8 lanes per dst, 4 dst/warp) ======================
__global__ __launch_bounds__(256) void agg2_kernel(const float* __restrict__ b2,
                                                   float* __restrict__ out) {
    int l = threadIdx.x & 31;
    int wid = threadIdx.x >> 5;
    int d = blockIdx.x * 32 + wid * 4 + (l >> 3);
    if (d >= NN) return;
    int sub = l & 7;
    int beg = d_rowptr[d], end = d_rowptr[d + 1];
    float erd = d_er2[d];
    float s = 0.f, a0 = 0.f, a1 = 0.f;
    for (int e = beg + sub; e < end; e += 8) {
        int si = d_esrc[e];
        float xv = d_el2[si] + erd;
        xv = xv > 0.f ? xv : 0.2f * xv;
        float ex = __expf(xv);
        s += ex;
        a0 = fmaf(ex, d_z2[2 * si + 0], a0);
        a1 = fmaf(ex, d_z2[2 * si + 1], a1);
    }
#pragma unroll
    for (int o = 4; o > 0; o >>= 1) {
        s  += __shfl_xor_sync(0xffffffffu, s, o);
        a0 += __shfl_xor_sync(0xffffffffu, a0, o);
        a1 += __shfl_xor_sync(0xffffffffu, a1, o);
    }
    if (sub == 0) {
        float o0, o1;
        if (s > 0.f) {
            o0 = a0 / s + b2[0];
            o1 = a1 / s + b2[1];
        } else {
            o0 = b2[0];
            o1 = b2[1];
        }
        out[2 * d + 0] = o0;
        out[2 * d + 1] = o1;
    }
}

// ====================== launch ======================
extern "C" void kernel_launch(void* const* d_in, const int* in_sizes, int n_in,
                              void* d_out, int out_size) {
    const float* x   = (const float*)d_in[0];
    const int*   src = (const int*)d_in[1];
    const int*   dst = (const int*)d_in[2];
    const float* W1  = (const float*)d_in[3];
    const float* al1 = (const float*)d_in[4];
    const float* ar1 = (const float*)d_in[5];
    const float* b1  = (const float*)d_in[6];
    const float* W2  = (const float*)d_in[7];
    const float* al2 = (const float*)d_in[8];
    const float* ar2 = (const float*)d_in[9];
    const float* b2  = (const float*)d_in[10];
    float* out = (float*)d_out;

    dim3 ggrid((NN + GBM - 1) / GBM, OUTD / GBN);   // 391 x 4
    gemm1_mma_kernel<<<ggrid, 256>>>(x, W1, al1, ar1);
    csr_build_kernel<<<NBLK, SCAN_B>>>(src, dst);
    agg1_kernel<<<(NN + 7) / 8, 256>>>(b1, W2, al2, ar2);
    agg2_kernel<<<(NN + 31) / 32, 256>>>(b2, out);
}

// round 12
// speedup vs baseline: 1.0345x; 1.0345x over previous
#include <cuda_runtime.h>
#include <cuda_bf16.h>
#include <cuda_fp16.h>
#include <math_constants.h>

#define NN 50000
#define EE 800000
#define INF_DIM 128
#define HH 8
#define FF 32
#define OUTD 256   // HH*FF
#define CC 2

#define SCAN_B 256
#define NBLK ((NN + SCAN_B - 1) / SCAN_B)   // 196

// -------- scratch (static __device__ globals; allocation-free) --------
__device__ __half d_zh[NN * OUTD];     // fp16 projected features (gather payload)
__device__ float  d_el[NN * HH];
__device__ float  d_er[NN * HH];
__device__ int    d_cnt[NN];
__device__ int    d_rowptr[NN + 1];
__device__ int    d_wp[NN];
__device__ int    d_esrc[EE];
__device__ int    d_bsum[NBLK];
__device__ float4 d_rec2[NN];          // (z2_0, z2_1, el2, er2) packed per node

// ====================== GEMM1 (tf32 MMA) + fused el/er epilogue ======================
#define GBM 128
#define GBN 64
#define KC 32

__device__ __forceinline__ unsigned f2tf32(float x) {
    unsigned u;
    asm("cvt.rna.tf32.f32 %0, %1;" : "=r"(u) : "f"(x));
    return u;
}

__global__ __launch_bounds__(256) void gemm1_mma_kernel(const float* __restrict__ A,
                                                        const float* __restrict__ B,
                                                        const float* __restrict__ al,
                                                        const float* __restrict__ ar) {
    __shared__ float As[GBM][KC + 4];
    __shared__ float Bs[KC][72];

    const int bm = blockIdx.x * GBM;
    const int bn = blockIdx.y * GBN;
    const int tid = threadIdx.x;
    const int wid = tid >> 5;
    const int l = tid & 31;
    const int wm = wid & 3;
    const int wn = wid >> 2;

    if (blockIdx.y == 0) {
        int gt = blockIdx.x * 256 + tid;
        if (gt < NN) d_cnt[gt] = 0;
    }

    float c[2][4][4];
#pragma unroll
    for (int mt = 0; mt < 2; mt++)
#pragma unroll
        for (int nt = 0; nt < 4; nt++)
#pragma unroll
            for (int r = 0; r < 4; r++) c[mt][nt][r] = 0.f;

    for (int kc = 0; kc < INF_DIM; kc += KC) {
#pragma unroll
        for (int i = 0; i < 4; i++) {
            int row = (tid >> 3) + i * 32;
            int col = (tid & 7) * 4;
            int grow = bm + row;
            float4 v = make_float4(0.f, 0.f, 0.f, 0.f);
            if (grow < NN) v = *(const float4*)(A + (size_t)grow * INF_DIM + kc + col);
            As[row][col + 0] = __uint_as_float(f2tf32(v.x));
            As[row][col + 1] = __uint_as_float(f2tf32(v.y));
            As[row][col + 2] = __uint_as_float(f2tf32(v.z));
            As[row][col + 3] = __uint_as_float(f2tf32(v.w));
        }
#pragma unroll
        for (int i = 0; i < 2; i++) {
            int k = (tid >> 4) + i * 16;
            int n = (tid & 15) * 4;
            float4 v = *(const float4*)(B + (size_t)(kc + k) * OUTD + bn + n);
            Bs[k][n + 0] = __uint_as_float(f2tf32(v.x));
            Bs[k][n + 1] = __uint_as_float(f2tf32(v.y));
            Bs[k][n + 2] = __uint_as_float(f2tf32(v.z));
            Bs[k][n + 3] = __uint_as_float(f2tf32(v.w));
        }
        __syncthreads();

        const int fr = l >> 2;
        const int fc = l & 3;
#pragma unroll
        for (int ks = 0; ks < KC; ks += 8) {
            unsigned a[2][4], b[4][2];
#pragma unroll
            for (int mt = 0; mt < 2; mt++) {
                int base = wm * 32 + mt * 16;
                a[mt][0] = __float_as_uint(As[base + fr][ks + fc]);
                a[mt][1] = __float_as_uint(As[base + fr + 8][ks + fc]);
                a[mt][2] = __float_as_uint(As[base + fr][ks + fc + 4]);
                a[mt][3] = __float_as_uint(As[base + fr + 8][ks + fc + 4]);
            }
#pragma unroll
            for (int nt = 0; nt < 4; nt++) {
                int coln = wn * 32 + nt * 8 + fr;
                b[nt][0] = __float_as_uint(Bs[ks + fc][coln]);
                b[nt][1] = __float_as_uint(Bs[ks + fc + 4][coln]);
            }
#pragma unroll
            for (int mt = 0; mt < 2; mt++)
#pragma unroll
                for (int nt = 0; nt < 4; nt++) {
                    asm volatile(
                        "mma.sync.aligned.m16n8k8.row.col.f32.tf32.tf32.f32 "
                        "{%0,%1,%2,%3}, {%4,%5,%6,%7}, {%8,%9}, {%0,%1,%2,%3};\n"
                        : "+f"(c[mt][nt][0]), "+f"(c[mt][nt][1]),
                          "+f"(c[mt][nt][2]), "+f"(c[mt][nt][3])
                        : "r"(a[mt][0]), "r"(a[mt][1]), "r"(a[mt][2]), "r"(a[mt][3]),
                          "r"(b[nt][0]), "r"(b[nt][1]));
                }
        }
        __syncthreads();
    }

    const int h = blockIdx.y * 2 + wn;
    const int fr = l >> 2;
    const int fc = l & 3;

    float alv[4][2], arv[4][2];
#pragma unroll
    for (int nt = 0; nt < 4; nt++) {
        int cih = nt * 8 + fc * 2;
        alv[nt][0] = al[h * FF + cih];
        alv[nt][1] = al[h * FF + cih + 1];
        arv[nt][0] = ar[h * FF + cih];
        arv[nt][1] = ar[h * FF + cih + 1];
    }

    float pel[2][2] = {{0.f, 0.f}, {0.f, 0.f}};
    float per[2][2] = {{0.f, 0.f}, {0.f, 0.f}};

#pragma unroll
    for (int mt = 0; mt < 2; mt++) {
        int r0 = bm + wm * 32 + mt * 16 + fr;
        int r1 = r0 + 8;
#pragma unroll
        for (int nt = 0; nt < 4; nt++) {
            float z00 = c[mt][nt][0], z01 = c[mt][nt][1];
            float z10 = c[mt][nt][2], z11 = c[mt][nt][3];
            pel[mt][0] += z00 * alv[nt][0] + z01 * alv[nt][1];
            pel[mt][1] += z10 * alv[nt][0] + z11 * alv[nt][1];
            per[mt][0] += z00 * arv[nt][0] + z01 * arv[nt][1];
            per[mt][1] += z10 * arv[nt][0] + z11 * arv[nt][1];
            int colg = bn + wn * 32 + nt * 8 + fc * 2;
            if (r0 < NN) *(__half2*)(d_zh + (size_t)r0 * OUTD + colg) = __floats2half2_rn(z00, z01);
            if (r1 < NN) *(__half2*)(d_zh + (size_t)r1 * OUTD + colg) = __floats2half2_rn(z10, z11);
        }
    }
#pragma unroll
    for (int o = 1; o < 4; o <<= 1) {
#pragma unroll
        for (int mt = 0; mt < 2; mt++) {
#pragma unroll
            for (int i = 0; i < 2; i++) {
                pel[mt][i] += __shfl_xor_sync(0xffffffffu, pel[mt][i], o);
                per[mt][i] += __shfl_xor_sync(0xffffffffu, per[mt][i], o);
            }
        }
    }
    if (fc == 0) {
#pragma unroll
        for (int mt = 0; mt < 2; mt++) {
#pragma unroll
            for (int i = 0; i < 2; i++) {
                int row = bm + wm * 32 + mt * 16 + fr + i * 8;
                if (row < NN) {
                    d_el[row * HH + h] = pel[mt][i];
                    d_er[row * HH + h] = per[mt][i];
                }
            }
        }
    }
}

// ====================== CSR build (4 separate kernels — measured best) ======================
__global__ void hist_kernel(const int* __restrict__ dst) {
    int e = blockIdx.x * blockDim.x + threadIdx.x;
    if (e < EE) atomicAdd(&d_cnt[dst[e]], 1);
}

__device__ __forceinline__ int warp_incl_scan(int v, int l) {
#pragma unroll
    for (int o = 1; o < 32; o <<= 1) {
        int u = __shfl_up_sync(0xffffffffu, v, o);
        if (l >= o) v += u;
    }
    return v;
}

__global__ __launch_bounds__(SCAN_B) void scan_blocks_kernel() {
    __shared__ int wsum[SCAN_B / 32];
    int t = threadIdx.x;
    int g = blockIdx.x * SCAN_B + t;
    int l = t & 31;
    int wid = t >> 5;
    int v = (g < NN) ? d_cnt[g] : 0;
    int inc = warp_incl_scan(v, l);
    if (l == 31) wsum[wid] = inc;
    __syncthreads();
    if (wid == 0) {
        int wv = (l < SCAN_B / 32) ? wsum[l] : 0;
        wv = warp_incl_scan(wv, l);
        if (l < SCAN_B / 32) wsum[l] = wv;
    }
    __syncthreads();
    int base = (wid == 0) ? 0 : wsum[wid - 1];
    int excl = base + inc - v;
    if (g < NN) d_rowptr[g] = excl;
    if (t == SCAN_B - 1) d_bsum[blockIdx.x] = base + inc;
}

// apply: each block needs only the SUM of preceding block totals -> in-block reduce
__global__ __launch_bounds__(SCAN_B) void scan_apply_kernel() {
    __shared__ int wred[SCAN_B / 32];
    __shared__ int soff;
    int t = threadIdx.x;
    int l = t & 31;
    int wid = t >> 5;
    int v = (t < blockIdx.x) ? d_bsum[t] : 0;   // NBLK=196 < 256
#pragma unroll
    for (int o = 16; o > 0; o >>= 1) v += __shfl_xor_sync(0xffffffffu, v, o);
    if (l == 0) wred[wid] = v;
    __syncthreads();
    if (t == 0) {
        int acc = 0;
#pragma unroll
        for (int i = 0; i < SCAN_B / 32; i++) acc += wred[i];
        soff = acc;
    }
    __syncthreads();
    int g = blockIdx.x * SCAN_B + t;
    if (g < NN) {
        int r = d_rowptr[g] + soff;
        d_rowptr[g] = r;
        d_wp[g] = r;
    }
    if (g == 0) d_rowptr[NN] = EE;
}

__global__ void fill_csr_kernel(const int* __restrict__ src, const int* __restrict__ dst) {
    int e = blockIdx.x * blockDim.x + threadIdx.x;
    if (e < EE) {
        int d = dst[e];
        int pos = atomicAdd(&d_wp[d], 1);
        d_esrc[pos] = src[e];
    }
}

__device__ __forceinline__ float elu_f(float x) { return x > 0.f ? x : expm1f(x); }

// ====================== K7: layer-1 aggregation + fused layer-2 projection ======================
// Plain-exp softmax (shift-invariance: max-subtraction unnecessary, logits bounded ~|15|).
// warp per dst node; lane l -> features l*8..l*8+7, head = l/4.
// Epilogue emits packed per-node record (z2_0, z2_1, el2, er2) for agg2's single-gather.
__global__ __launch_bounds__(256) void agg1_kernel(const float* __restrict__ b1,
                                                   const float* __restrict__ W2,
                                                   const float* __restrict__ al2,
                                                   const float* __restrict__ ar2) {
    int w = blockIdx.x * 8 + (threadIdx.x >> 5);
    if (w >= NN) return;
    int l = threadIdx.x & 31;
    int hh = l >> 2;
    int beg = d_rowptr[w], end = d_rowptr[w + 1];

    float o[8];
    const float* bb = b1 + l * 8;

    if (beg == end) {
#pragma unroll
        for (int i = 0; i < 8; i++) o[i] = elu_f(bb[i]);
    } else {
        float er_h = d_er[w * HH + hh];
        float s = 0.f;
        float acc[8];
#pragma unroll
        for (int i = 0; i < 8; i++) acc[i] = 0.f;

#pragma unroll 4
        for (int e = beg; e < end; e++) {
            int si = __ldg(&d_esrc[e]);
            float xv = __ldg(&d_el[si * HH + hh]) + er_h;
            xv = xv > 0.f ? xv : 0.2f * xv;
            float ex = __expf(xv);
            s += ex;
            uint4 raw = *(const uint4*)(d_zh + (size_t)si * OUTD + l * 8);
            float2 z0 = __half22float2(*(const __half2*)&raw.x);
            float2 z1 = __half22float2(*(const __half2*)&raw.y);
            float2 z2 = __half22float2(*(const __half2*)&raw.z);
            float2 z3 = __half22float2(*(const __half2*)&raw.w);
            acc[0] = fmaf(ex, z0.x, acc[0]);
            acc[1] = fmaf(ex, z0.y, acc[1]);
            acc[2] = fmaf(ex, z1.x, acc[2]);
            acc[3] = fmaf(ex, z1.y, acc[3]);
            acc[4] = fmaf(ex, z2.x, acc[4]);
            acc[5] = fmaf(ex, z2.y, acc[5]);
            acc[6] = fmaf(ex, z3.x, acc[6]);
            acc[7] = fmaf(ex, z3.y, acc[7]);
        }
        float inv_s = 1.f / s;
#pragma unroll
        for (int i = 0; i < 8; i++) o[i] = elu_f(fmaf(acc[i], inv_s, bb[i]));
    }

    // ---- fused layer-2 projection: z2 = h @ W2, h held across the warp ----
    float pz0, pz1;
    const float4* W2v = (const float4*)(W2 + l * 16);  // 8 cols x 2 = 16 floats per lane
    float4 w0 = W2v[0], w1 = W2v[1], w2 = W2v[2], w3 = W2v[3];
    pz0 = o[0] * w0.x + o[1] * w0.z + o[2] * w1.x + o[3] * w1.z +
          o[4] * w2.x + o[5] * w2.z + o[6] * w3.x + o[7] * w3.z;
    pz1 = o[0] * w0.y + o[1] * w0.w + o[2] * w1.y + o[3] * w1.w +
          o[4] * w2.y + o[5] * w2.w + o[6] * w3.y + o[7] * w3.w;
#pragma unroll
    for (int sh = 16; sh > 0; sh >>= 1) {
        pz0 += __shfl_xor_sync(0xffffffffu, pz0, sh);
        pz1 += __shfl_xor_sync(0xffffffffu, pz1, sh);
    }
    if (l == 0) {
        float el2v = pz0 * al2[0] + pz1 * al2[1];
        float er2v = pz0 * ar2[0] + pz1 * ar2[1];
        d_rec2[w] = make_float4(pz0, pz1, el2v, er2v);
    }
}

// ====================== K9: layer-2 aggregation (8 lanes per dst, 4 dst/warp) ======================
// One 16B record gather per edge (z2_0, z2_1, el2, er2) instead of 3 scalar gathers.
__global__ __launch_bounds__(256) void agg2_kernel(const float* __restrict__ b2,
                                                   float* __restrict__ out) {
    int l = threadIdx.x & 31;
    int wid = threadIdx.x >> 5;
    int d = blockIdx.x * 32 + wid * 4 + (l >> 3);
    if (d >= NN) return;
    int sub = l & 7;
    int beg = d_rowptr[d], end = d_rowptr[d + 1];
    float erd = d_rec2[d].w;
    float s = 0.f, a0 = 0.f, a1 = 0.f;
    for (int e = beg + sub; e < end; e += 8) {
        int si = __ldg(&d_esrc[e]);
        float4 r = d_rec2[si];
        float xv = r.z + erd;
        xv = xv > 0.f ? xv : 0.2f * xv;
        float ex = __expf(xv);
        s += ex;
        a0 = fmaf(ex, r.x, a0);
        a1 = fmaf(ex, r.y, a1);
    }
#pragma unroll
    for (int o = 4; o > 0; o >>= 1) {
        s  += __shfl_xor_sync(0xffffffffu, s, o);
        a0 += __shfl_xor_sync(0xffffffffu, a0, o);
        a1 += __shfl_xor_sync(0xffffffffu, a1, o);
    }
    if (sub == 0) {
        float o0, o1;
        if (s > 0.f) {
            o0 = a0 / s + b2[0];
            o1 = a1 / s + b2[1];
        } else {
            o0 = b2[0];
            o1 = b2[1];
        }
        out[2 * d + 0] = o0;
        out[2 * d + 1] = o1;
    }
}

// ====================== launch ======================
extern "C" void kernel_launch(void* const* d_in, const int* in_sizes, int n_in,
                              void* d_out, int out_size) {
    const float* x   = (const float*)d_in[0];
    const int*   src = (const int*)d_in[1];
    const int*   dst = (const int*)d_in[2];
    const float* W1  = (const float*)d_in[3];
    const float* al1 = (const float*)d_in[4];
    const float* ar1 = (const float*)d_in[5];
    const float* b1  = (const float*)d_in[6];
    const float* W2  = (const float*)d_in[7];
    const float* al2 = (const float*)d_in[8];
    const float* ar2 = (const float*)d_in[9];
    const float* b2  = (const float*)d_in[10];
    float* out = (float*)d_out;

    dim3 ggrid((NN + GBM - 1) / GBM, OUTD / GBN);   // 391 x 4
    gemm1_mma_kernel<<<ggrid, 256>>>(x, W1, al1, ar1);
    hist_kernel<<<(EE + 255) / 256, 256>>>(dst);
    scan_blocks_kernel<<<NBLK, SCAN_B>>>();
    scan_apply_kernel<<<NBLK, SCAN_B>>>();
    fill_csr_kernel<<<(EE + 255) / 256, 256>>>(src, dst);
    agg1_kernel<<<(NN + 7) / 8, 256>>>(b1, W2, al2, ar2);
    agg2_kernel<<<(NN + 31) / 32, 256>>>(b2, out);
}

// round 13
// speedup vs baseline: 1.0502x; 1.0152x over previous
#include <cuda_runtime.h>
#include <cuda_bf16.h>
#include <cuda_fp16.h>
#include <math_constants.h>

#define NN 50000
#define EE 800000
#define INF_DIM 128
#define HH 8
#define FF 32
#define OUTD 256   // HH*FF
#define CC 2

#define SCAN_B 256
#define NBLK ((NN + SCAN_B - 1) / SCAN_B)   // 196

// -------- scratch (static __device__ globals; allocation-free) --------
__device__ __half d_zh[NN * OUTD];     // fp16 projected features (gather payload)
__device__ float  d_el[NN * HH];
__device__ float  d_er[NN * HH];
__device__ int    d_cnt[NN];           // zero on entry every run (BSS init + zero-after-read in scan)
__device__ int    d_rowptr[NN + 1];
__device__ int    d_wp[NN];
__device__ int    d_esrc[EE];
__device__ int    d_bsum[NBLK];
__device__ int    d_sbar[2];           // scan grid-barrier: [0]=arrive, [1]=exit (self-resetting)
__device__ float4 d_rec2[NN];          // (z2_0, z2_1, el2, er2) packed per node

// ====================== GEMM1 (tf32 MMA) + fused el/er epilogue + fused histogram ======================
#define GBM 128
#define GBN 64
#define KC 32

__device__ __forceinline__ unsigned f2tf32(float x) {
    unsigned u;
    asm("cvt.rna.tf32.f32 %0, %1;" : "=r"(u) : "f"(x));
    return u;
}

__global__ __launch_bounds__(256) void gemm1_mma_kernel(const float* __restrict__ A,
                                                        const float* __restrict__ B,
                                                        const float* __restrict__ al,
                                                        const float* __restrict__ ar,
                                                        const int* __restrict__ dst) {
    __shared__ float As[GBM][KC + 4];
    __shared__ float Bs[KC][72];

    const int bm = blockIdx.x * GBM;
    const int bn = blockIdx.y * GBN;
    const int tid = threadIdx.x;
    const int wid = tid >> 5;
    const int l = tid & 31;
    const int wm = wid & 3;
    const int wn = wid >> 2;

    // fused histogram: d_cnt is guaranteed zero at kernel entry (zeroed by scan
    // in the previous replay; BSS zero-init on the first run). Fire-and-forget
    // RED atomics overlap with the MMA mainloop below.
    {
        const int gstride = gridDim.x * gridDim.y * 256;
        int gt = (blockIdx.y * gridDim.x + blockIdx.x) * 256 + tid;
        for (int e = gt; e < EE; e += gstride)
            atomicAdd(&d_cnt[dst[e]], 1);
    }

    float c[2][4][4];
#pragma unroll
    for (int mt = 0; mt < 2; mt++)
#pragma unroll
        for (int nt = 0; nt < 4; nt++)
#pragma unroll
            for (int r = 0; r < 4; r++) c[mt][nt][r] = 0.f;

    for (int kc = 0; kc < INF_DIM; kc += KC) {
#pragma unroll
        for (int i = 0; i < 4; i++) {
            int row = (tid >> 3) + i * 32;
            int col = (tid & 7) * 4;
            int grow = bm + row;
            float4 v = make_float4(0.f, 0.f, 0.f, 0.f);
            if (grow < NN) v = *(const float4*)(A + (size_t)grow * INF_DIM + kc + col);
            As[row][col + 0] = __uint_as_float(f2tf32(v.x));
            As[row][col + 1] = __uint_as_float(f2tf32(v.y));
            As[row][col + 2] = __uint_as_float(f2tf32(v.z));
            As[row][col + 3] = __uint_as_float(f2tf32(v.w));
        }
#pragma unroll
        for (int i = 0; i < 2; i++) {
            int k = (tid >> 4) + i * 16;
            int n = (tid & 15) * 4;
            float4 v = *(const float4*)(B + (size_t)(kc + k) * OUTD + bn + n);
            Bs[k][n + 0] = __uint_as_float(f2tf32(v.x));
            Bs[k][n + 1] = __uint_as_float(f2tf32(v.y));
            Bs[k][n + 2] = __uint_as_float(f2tf32(v.z));
            Bs[k][n + 3] = __uint_as_float(f2tf32(v.w));
        }
        __syncthreads();

        const int fr = l >> 2;
        const int fc = l & 3;
#pragma unroll
        for (int ks = 0; ks < KC; ks += 8) {
            unsigned a[2][4], b[4][2];
#pragma unroll
            for (int mt = 0; mt < 2; mt++) {
                int base = wm * 32 + mt * 16;
                a[mt][0] = __float_as_uint(As[base + fr][ks + fc]);
                a[mt][1] = __float_as_uint(As[base + fr + 8][ks + fc]);
                a[mt][2] = __float_as_uint(As[base + fr][ks + fc + 4]);
                a[mt][3] = __float_as_uint(As[base + fr + 8][ks + fc + 4]);
            }
#pragma unroll
            for (int nt = 0; nt < 4; nt++) {
                int coln = wn * 32 + nt * 8 + fr;
                b[nt][0] = __float_as_uint(Bs[ks + fc][coln]);
                b[nt][1] = __float_as_uint(Bs[ks + fc + 4][coln]);
            }
#pragma unroll
            for (int mt = 0; mt < 2; mt++)
#pragma unroll
                for (int nt = 0; nt < 4; nt++) {
                    asm volatile(
                        "mma.sync.aligned.m16n8k8.row.col.f32.tf32.tf32.f32 "
                        "{%0,%1,%2,%3}, {%4,%5,%6,%7}, {%8,%9}, {%0,%1,%2,%3};\n"
                        : "+f"(c[mt][nt][0]), "+f"(c[mt][nt][1]),
                          "+f"(c[mt][nt][2]), "+f"(c[mt][nt][3])
                        : "r"(a[mt][0]), "r"(a[mt][1]), "r"(a[mt][2]), "r"(a[mt][3]),
                          "r"(b[nt][0]), "r"(b[nt][1]));
                }
        }
        __syncthreads();
    }

    const int h = blockIdx.y * 2 + wn;
    const int fr = l >> 2;
    const int fc = l & 3;

    float alv[4][2], arv[4][2];
#pragma unroll
    for (int nt = 0; nt < 4; nt++) {
        int cih = nt * 8 + fc * 2;
        alv[nt][0] = al[h * FF + cih];
        alv[nt][1] = al[h * FF + cih + 1];
        arv[nt][0] = ar[h * FF + cih];
        arv[nt][1] = ar[h * FF + cih + 1];
    }

    float pel[2][2] = {{0.f, 0.f}, {0.f, 0.f}};
    float per[2][2] = {{0.f, 0.f}, {0.f, 0.f}};

#pragma unroll
    for (int mt = 0; mt < 2; mt++) {
        int r0 = bm + wm * 32 + mt * 16 + fr;
        int r1 = r0 + 8;
#pragma unroll
        for (int nt = 0; nt < 4; nt++) {
            float z00 = c[mt][nt][0], z01 = c[mt][nt][1];
            float z10 = c[mt][nt][2], z11 = c[mt][nt][3];
            pel[mt][0] += z00 * alv[nt][0] + z01 * alv[nt][1];
            pel[mt][1] += z10 * alv[nt][0] + z11 * alv[nt][1];
            per[mt][0] += z00 * arv[nt][0] + z01 * arv[nt][1];
            per[mt][1] += z10 * arv[nt][0] + z11 * arv[nt][1];
            int colg = bn + wn * 32 + nt * 8 + fc * 2;
            if (r0 < NN) *(__half2*)(d_zh + (size_t)r0 * OUTD + colg) = __floats2half2_rn(z00, z01);
            if (r1 < NN) *(__half2*)(d_zh + (size_t)r1 * OUTD + colg) = __floats2half2_rn(z10, z11);
        }
    }
#pragma unroll
    for (int o = 1; o < 4; o <<= 1) {
#pragma unroll
        for (int mt = 0; mt < 2; mt++) {
#pragma unroll
            for (int i = 0; i < 2; i++) {
                pel[mt][i] += __shfl_xor_sync(0xffffffffu, pel[mt][i], o);
                per[mt][i] += __shfl_xor_sync(0xffffffffu, per[mt][i], o);
            }
        }
    }
    if (fc == 0) {
#pragma unroll
        for (int mt = 0; mt < 2; mt++) {
#pragma unroll
            for (int i = 0; i < 2; i++) {
                int row = bm + wm * 32 + mt * 16 + fr + i * 8;
                if (row < NN) {
                    d_el[row * HH + h] = pel[mt][i];
                    d_er[row * HH + h] = per[mt][i];
                }
            }
        }
    }
}

// ====================== merged scan: block scan + grid barrier + lookback apply ======================
__device__ __forceinline__ int warp_incl_scan(int v, int l) {
#pragma unroll
    for (int o = 1; o < 32; o <<= 1) {
        int u = __shfl_up_sync(0xffffffffu, v, o);
        if (l >= o) v += u;
    }
    return v;
}

// 196 blocks x 256 threads, 1 barrier. Replay-safe reset: blocks register exit
// AFTER passing the spin; the last exiter (all blocks provably past the spin)
// resets both counters for the next graph replay.
__device__ __forceinline__ void scan_grid_barrier() {
    __syncthreads();
    if (threadIdx.x == 0) {
        __threadfence();
        atomicAdd(&d_sbar[0], 1);
        while (atomicAdd(&d_sbar[0], 0) < NBLK) {}
        __threadfence();
        int ex = atomicAdd(&d_sbar[1], 1);
        if (ex == NBLK - 1) {
            d_sbar[0] = 0;
            d_sbar[1] = 0;
            __threadfence();
        }
    }
    __syncthreads();
}

__global__ __launch_bounds__(SCAN_B) void scan_kernel() {
    const int t = threadIdx.x;
    const int g = blockIdx.x * SCAN_B + t;
    const int l = t & 31;
    const int wid = t >> 5;

    // --- phase 1: block-local exclusive scan; zero-after-read resets d_cnt for next replay ---
    __shared__ int wsum[SCAN_B / 32];
    int v = (g < NN) ? d_cnt[g] : 0;
    if (g < NN) d_cnt[g] = 0;
    int inc = warp_incl_scan(v, l);
    if (l == 31) wsum[wid] = inc;
    __syncthreads();
    if (wid == 0) {
        int wv = (l < SCAN_B / 32) ? wsum[l] : 0;
        wv = warp_incl_scan(wv, l);
        if (l < SCAN_B / 32) wsum[l] = wv;
    }
    __syncthreads();
    int base = (wid == 0) ? 0 : wsum[wid - 1];
    int excl = base + inc - v;
    if (t == SCAN_B - 1) d_bsum[blockIdx.x] = base + inc;

    scan_grid_barrier();

    // --- phase 2: lookback sum of preceding block totals, apply ---
    __shared__ int wred[SCAN_B / 32];
    __shared__ int soff;
    int pv = (t < blockIdx.x) ? d_bsum[t] : 0;   // NBLK=196 < 256
#pragma unroll
    for (int o = 16; o > 0; o >>= 1) pv += __shfl_xor_sync(0xffffffffu, pv, o);
    if (l == 0) wred[wid] = pv;
    __syncthreads();
    if (t == 0) {
        int acc = 0;
#pragma unroll
        for (int i = 0; i < SCAN_B / 32; i++) acc += wred[i];
        soff = acc;
    }
    __syncthreads();
    if (g < NN) {
        int r = excl + soff;
        d_rowptr[g] = r;
        d_wp[g] = r;
    }
    if (g == 0) d_rowptr[NN] = EE;
}

__global__ void fill_csr_kernel(const int* __restrict__ src, const int* __restrict__ dst) {
    int e = blockIdx.x * blockDim.x + threadIdx.x;
    if (e < EE) {
        int d = dst[e];
        int pos = atomicAdd(&d_wp[d], 1);
        d_esrc[pos] = src[e];
    }
}

__device__ __forceinline__ float elu_f(float x) { return x > 0.f ? x : expm1f(x); }

// ====================== K7: layer-1 aggregation + fused layer-2 projection ======================
// Plain-exp softmax (shift-invariance: max-subtraction unnecessary, logits bounded ~|15|).
// warp per dst node; lane l -> features l*8..l*8+7, head = l/4.
// Epilogue emits packed per-node record (z2_0, z2_1, el2, er2) for agg2's single-gather.
__global__ __launch_bounds__(256) void agg1_kernel(const float* __restrict__ b1,
                                                   const float* __restrict__ W2,
                                                   const float* __restrict__ al2,
                                                   const float* __restrict__ ar2) {
    int w = blockIdx.x * 8 + (threadIdx.x >> 5);
    if (w >= NN) return;
    int l = threadIdx.x & 31;
    int hh = l >> 2;
    int beg = d_rowptr[w], end = d_rowptr[w + 1];

    float o[8];
    const float* bb = b1 + l * 8;

    if (beg == end) {
#pragma unroll
        for (int i = 0; i < 8; i++) o[i] = elu_f(bb[i]);
    } else {
        float er_h = d_er[w * HH + hh];
        float s = 0.f;
        float acc[8];
#pragma unroll
        for (int i = 0; i < 8; i++) acc[i] = 0.f;

#pragma unroll 4
        for (int e = beg; e < end; e++) {
            int si = __ldg(&d_esrc[e]);
            float xv = __ldg(&d_el[si * HH + hh]) + er_h;
            xv = xv > 0.f ? xv : 0.2f * xv;
            float ex = __expf(xv);
            s += ex;
            uint4 raw = *(const uint4*)(d_zh + (size_t)si * OUTD + l * 8);
            float2 z0 = __half22float2(*(const __half2*)&raw.x);
            float2 z1 = __half22float2(*(const __half2*)&raw.y);
            float2 z2 = __half22float2(*(const __half2*)&raw.z);
            float2 z3 = __half22float2(*(const __half2*)&raw.w);
            acc[0] = fmaf(ex, z0.x, acc[0]);
            acc[1] = fmaf(ex, z0.y, acc[1]);
            acc[2] = fmaf(ex, z1.x, acc[2]);
            acc[3] = fmaf(ex, z1.y, acc[3]);
            acc[4] = fmaf(ex, z2.x, acc[4]);
            acc[5] = fmaf(ex, z2.y, acc[5]);
            acc[6] = fmaf(ex, z3.x, acc[6]);
            acc[7] = fmaf(ex, z3.y, acc[7]);
        }
        float inv_s = 1.f / s;
#pragma unroll
        for (int i = 0; i < 8; i++) o[i] = elu_f(fmaf(acc[i], inv_s, bb[i]));
    }

    // ---- fused layer-2 projection: z2 = h @ W2, h held across the warp ----
    float pz0, pz1;
    const float4* W2v = (const float4*)(W2 + l * 16);  // 8 cols x 2 = 16 floats per lane
    float4 w0 = W2v[0], w1 = W2v[1], w2 = W2v[2], w3 = W2v[3];
    pz0 = o[0] * w0.x + o[1] * w0.z + o[2] * w1.x + o[3] * w1.z +
          o[4] * w2.x + o[5] * w2.z + o[6] * w3.x + o[7] * w3.z;
    pz1 = o[0] * w0.y + o[1] * w0.w + o[2] * w1.y + o[3] * w1.w +
          o[4] * w2.y + o[5] * w2.w + o[6] * w3.y + o[7] * w3.w;
#pragma unroll
    for (int sh = 16; sh > 0; sh >>= 1) {
        pz0 += __shfl_xor_sync(0xffffffffu, pz0, sh);
        pz1 += __shfl_xor_sync(0xffffffffu, pz1, sh);
    }
    if (l == 0) {
        float el2v = pz0 * al2[0] + pz1 * al2[1];
        float er2v = pz0 * ar2[0] + pz1 * ar2[1];
        d_rec2[w] = make_float4(pz0, pz1, el2v, er2v);
    }
}

// ====================== K9: layer-2 aggregation (8 lanes per dst, 4 dst/warp) ======================
// One 16B record gather per edge (z2_0, z2_1, el2, er2) instead of 3 scalar gathers.
__global__ __launch_bounds__(256) void agg2_kernel(const float* __restrict__ b2,
                                                   float* __restrict__ out) {
    int l = threadIdx.x & 31;
    int wid = threadIdx.x >> 5;
    int d = blockIdx.x * 32 + wid * 4 + (l >> 3);
    if (d >= NN) return;
    int sub = l & 7;
    int beg = d_rowptr[d], end = d_rowptr[d + 1];
    float erd = d_rec2[d].w;
    float s = 0.f, a0 = 0.f, a1 = 0.f;
    for (int e = beg + sub; e < end; e += 8) {
        int si = __ldg(&d_esrc[e]);
        float4 r = d_rec2[si];
        float xv = r.z + erd;
        xv = xv > 0.f ? xv : 0.2f * xv;
        float ex = __expf(xv);
        s += ex;
        a0 = fmaf(ex, r.x, a0);
        a1 = fmaf(ex, r.y, a1);
    }
#pragma unroll
    for (int o = 4; o > 0; o >>= 1) {
        s  += __shfl_xor_sync(0xffffffffu, s, o);
        a0 += __shfl_xor_sync(0xffffffffu, a0, o);
        a1 += __shfl_xor_sync(0xffffffffu, a1, o);
    }
    if (sub == 0) {
        float o0, o1;
        if (s > 0.f) {
            o0 = a0 / s + b2[0];
            o1 = a1 / s + b2[1];
        } else {
            o0 = b2[0];
            o1 = b2[1];
        }
        out[2 * d + 0] = o0;
        out[2 * d + 1] = o1;
    }
}

// ====================== launch ======================
extern "C" void kernel_launch(void* const* d_in, const int* in_sizes, int n_in,
                              void* d_out, int out_size) {
    const float* x   = (const float*)d_in[0];
    const int*   src = (const int*)d_in[1];
    const int*   dst = (const int*)d_in[2];
    const float* W1  = (const float*)d_in[3];
    const float* al1 = (const float*)d_in[4];
    const float* ar1 = (const float*)d_in[5];
    const float* b1  = (const float*)d_in[6];
    const float* W2  = (const float*)d_in[7];
    const float* al2 = (const float*)d_in[8];
    const float* ar2 = (const float*)d_in[9];
    const float* b2  = (const float*)d_in[10];
    float* out = (float*)d_out;

    dim3 ggrid((NN + GBM - 1) / GBM, OUTD / GBN);   // 391 x 4
    gemm1_mma_kernel<<<ggrid, 256>>>(x, W1, al1, ar1, dst);
    scan_kernel<<<NBLK, SCAN_B>>>();
    fill_csr_kernel<<<(EE + 255) / 256, 256>>>(src, dst);
    agg1_kernel<<<(NN + 7) / 8, 256>>>(b1, W2, al2, ar2);
    agg2_kernel<<<(NN + 31) / 32, 256>>>(b2, out);
}

// round 14
// speedup vs baseline: 1.0825x; 1.0307x over previous
#include <cuda_runtime.h>
#include <cuda_bf16.h>
#include <cuda_fp16.h>
#include <math_constants.h>

#define NN 50000
#define EE 800000
#define INF_DIM 128
#define HH 8
#define FF 32
#define OUTD 256   // HH*FF
#define CC 2

#define SCAN_B 256
#define NBLK ((NN + SCAN_B - 1) / SCAN_B)   // 196

// -------- scratch (static __device__ globals; allocation-free) --------
__device__ __half d_zh[NN * OUTD];     // fp16 projected features (gather payload)
__device__ float  d_el[NN * HH];
__device__ float  d_er[NN * HH];
__device__ int    d_cnt[NN];           // zero on entry every run (BSS init + zero-after-read in scan)
__device__ int    d_rank[EE];          // per-edge rank within its dst (from hist atomics)
__device__ int    d_rowptr[NN + 1];
__device__ int    d_esrc[EE];
__device__ int    d_bsum[NBLK];
__device__ int    d_sbar[2];           // scan grid-barrier: [0]=arrive, [1]=exit (self-resetting)
__device__ float4 d_rec2[NN];          // (z2_0, z2_1, el2, er2) packed per node

// ====================== GEMM1 (tf32 MMA) + fused el/er epilogue + fused histogram ======================
#define GBM 128
#define GBN 64
#define KC 32

__device__ __forceinline__ unsigned f2tf32(float x) {
    unsigned u;
    asm("cvt.rna.tf32.f32 %0, %1;" : "=r"(u) : "f"(x));
    return u;
}

__global__ __launch_bounds__(256) void gemm1_mma_kernel(const float* __restrict__ A,
                                                        const float* __restrict__ B,
                                                        const float* __restrict__ al,
                                                        const float* __restrict__ ar,
                                                        const int* __restrict__ dst) {
    __shared__ float As[GBM][KC + 4];
    __shared__ float Bs[KC][72];

    const int bm = blockIdx.x * GBM;
    const int bn = blockIdx.y * GBN;
    const int tid = threadIdx.x;
    const int wid = tid >> 5;
    const int l = tid & 31;
    const int wm = wid & 3;
    const int wn = wid >> 2;

    // fused histogram + rank assignment: d_cnt is zero at entry (zeroed by scan
    // in the previous replay; BSS zero-init first run). The atomic's return value
    // is this edge's rank within its dst -> enables atomic-free fill.
    {
        const int gstride = gridDim.x * gridDim.y * 256;
        int gt = (blockIdx.y * gridDim.x + blockIdx.x) * 256 + tid;
        for (int e = gt; e < EE; e += gstride) {
            int r = atomicAdd(&d_cnt[dst[e]], 1);
            d_rank[e] = r;
        }
    }

    float c[2][4][4];
#pragma unroll
    for (int mt = 0; mt < 2; mt++)
#pragma unroll
        for (int nt = 0; nt < 4; nt++)
#pragma unroll
            for (int r = 0; r < 4; r++) c[mt][nt][r] = 0.f;

    for (int kc = 0; kc < INF_DIM; kc += KC) {
#pragma unroll
        for (int i = 0; i < 4; i++) {
            int row = (tid >> 3) + i * 32;
            int col = (tid & 7) * 4;
            int grow = bm + row;
            float4 v = make_float4(0.f, 0.f, 0.f, 0.f);
            if (grow < NN) v = *(const float4*)(A + (size_t)grow * INF_DIM + kc + col);
            As[row][col + 0] = __uint_as_float(f2tf32(v.x));
            As[row][col + 1] = __uint_as_float(f2tf32(v.y));
            As[row][col + 2] = __uint_as_float(f2tf32(v.z));
            As[row][col + 3] = __uint_as_float(f2tf32(v.w));
        }
#pragma unroll
        for (int i = 0; i < 2; i++) {
            int k = (tid >> 4) + i * 16;
            int n = (tid & 15) * 4;
            float4 v = *(const float4*)(B + (size_t)(kc + k) * OUTD + bn + n);
            Bs[k][n + 0] = __uint_as_float(f2tf32(v.x));
            Bs[k][n + 1] = __uint_as_float(f2tf32(v.y));
            Bs[k][n + 2] = __uint_as_float(f2tf32(v.z));
            Bs[k][n + 3] = __uint_as_float(f2tf32(v.w));
        }
        __syncthreads();

        const int fr = l >> 2;
        const int fc = l & 3;
#pragma unroll
        for (int ks = 0; ks < KC; ks += 8) {
            unsigned a[2][4], b[4][2];
#pragma unroll
            for (int mt = 0; mt < 2; mt++) {
                int base = wm * 32 + mt * 16;
                a[mt][0] = __float_as_uint(As[base + fr][ks + fc]);
                a[mt][1] = __float_as_uint(As[base + fr + 8][ks + fc]);
                a[mt][2] = __float_as_uint(As[base + fr][ks + fc + 4]);
                a[mt][3] = __float_as_uint(As[base + fr + 8][ks + fc + 4]);
            }
#pragma unroll
            for (int nt = 0; nt < 4; nt++) {
                int coln = wn * 32 + nt * 8 + fr;
                b[nt][0] = __float_as_uint(Bs[ks + fc][coln]);
                b[nt][1] = __float_as_uint(Bs[ks + fc + 4][coln]);
            }
#pragma unroll
            for (int mt = 0; mt < 2; mt++)
#pragma unroll
                for (int nt = 0; nt < 4; nt++) {
                    asm volatile(
                        "mma.sync.aligned.m16n8k8.row.col.f32.tf32.tf32.f32 "
                        "{%0,%1,%2,%3}, {%4,%5,%6,%7}, {%8,%9}, {%0,%1,%2,%3};\n"
                        : "+f"(c[mt][nt][0]), "+f"(c[mt][nt][1]),
                          "+f"(c[mt][nt][2]), "+f"(c[mt][nt][3])
                        : "r"(a[mt][0]), "r"(a[mt][1]), "r"(a[mt][2]), "r"(a[mt][3]),
                          "r"(b[nt][0]), "r"(b[nt][1]));
                }
        }
        __syncthreads();
    }

    const int h = blockIdx.y * 2 + wn;
    const int fr = l >> 2;
    const int fc = l & 3;

    float alv[4][2], arv[4][2];
#pragma unroll
    for (int nt = 0; nt < 4; nt++) {
        int cih = nt * 8 + fc * 2;
        alv[nt][0] = al[h * FF + cih];
        alv[nt][1] = al[h * FF + cih + 1];
        arv[nt][0] = ar[h * FF + cih];
        arv[nt][1] = ar[h * FF + cih + 1];
    }

    float pel[2][2] = {{0.f, 0.f}, {0.f, 0.f}};
    float per[2][2] = {{0.f, 0.f}, {0.f, 0.f}};

#pragma unroll
    for (int mt = 0; mt < 2; mt++) {
        int r0 = bm + wm * 32 + mt * 16 + fr;
        int r1 = r0 + 8;
#pragma unroll
        for (int nt = 0; nt < 4; nt++) {
            float z00 = c[mt][nt][0], z01 = c[mt][nt][1];
            float z10 = c[mt][nt][2], z11 = c[mt][nt][3];
            pel[mt][0] += z00 * alv[nt][0] + z01 * alv[nt][1];
            pel[mt][1] += z10 * alv[nt][0] + z11 * alv[nt][1];
            per[mt][0] += z00 * arv[nt][0] + z01 * arv[nt][1];
            per[mt][1] += z10 * arv[nt][0] + z11 * arv[nt][1];
            int colg = bn + wn * 32 + nt * 8 + fc * 2;
            if (r0 < NN) *(__half2*)(d_zh + (size_t)r0 * OUTD + colg) = __floats2half2_rn(z00, z01);
            if (r1 < NN) *(__half2*)(d_zh + (size_t)r1 * OUTD + colg) = __floats2half2_rn(z10, z11);
        }
    }
#pragma unroll
    for (int o = 1; o < 4; o <<= 1) {
#pragma unroll
        for (int mt = 0; mt < 2; mt++) {
#pragma unroll
            for (int i = 0; i < 2; i++) {
                pel[mt][i] += __shfl_xor_sync(0xffffffffu, pel[mt][i], o);
                per[mt][i] += __shfl_xor_sync(0xffffffffu, per[mt][i], o);
            }
        }
    }
    if (fc == 0) {
#pragma unroll
        for (int mt = 0; mt < 2; mt++) {
#pragma unroll
            for (int i = 0; i < 2; i++) {
                int row = bm + wm * 32 + mt * 16 + fr + i * 8;
                if (row < NN) {
                    d_el[row * HH + h] = pel[mt][i];
                    d_er[row * HH + h] = per[mt][i];
                }
            }
        }
    }
}

// ====================== merged scan: block scan + grid barrier + lookback apply ======================
__device__ __forceinline__ int warp_incl_scan(int v, int l) {
#pragma unroll
    for (int o = 1; o < 32; o <<= 1) {
        int u = __shfl_up_sync(0xffffffffu, v, o);
        if (l >= o) v += u;
    }
    return v;
}

// 196 blocks x 256 threads, 1 barrier. Replay-safe reset: blocks register exit
// AFTER passing the spin; the last exiter resets both counters.
__device__ __forceinline__ void scan_grid_barrier() {
    __syncthreads();
    if (threadIdx.x == 0) {
        __threadfence();
        atomicAdd(&d_sbar[0], 1);
        while (atomicAdd(&d_sbar[0], 0) < NBLK) {}
        __threadfence();
        int ex = atomicAdd(&d_sbar[1], 1);
        if (ex == NBLK - 1) {
            d_sbar[0] = 0;
            d_sbar[1] = 0;
            __threadfence();
        }
    }
    __syncthreads();
}

__global__ __launch_bounds__(SCAN_B) void scan_kernel() {
    const int t = threadIdx.x;
    const int g = blockIdx.x * SCAN_B + t;
    const int l = t & 31;
    const int wid = t >> 5;

    // --- phase 1: block-local exclusive scan; zero-after-read resets d_cnt for next replay ---
    __shared__ int wsum[SCAN_B / 32];
    int v = (g < NN) ? d_cnt[g] : 0;
    if (g < NN) d_cnt[g] = 0;
    int inc = warp_incl_scan(v, l);
    if (l == 31) wsum[wid] = inc;
    __syncthreads();
    if (wid == 0) {
        int wv = (l < SCAN_B / 32) ? wsum[l] : 0;
        wv = warp_incl_scan(wv, l);
        if (l < SCAN_B / 32) wsum[l] = wv;
    }
    __syncthreads();
    int base = (wid == 0) ? 0 : wsum[wid - 1];
    int excl = base + inc - v;
    if (t == SCAN_B - 1) d_bsum[blockIdx.x] = base + inc;

    scan_grid_barrier();

    // --- phase 2: lookback sum of preceding block totals, apply ---
    __shared__ int wred[SCAN_B / 32];
    __shared__ int soff;
    int pv = (t < blockIdx.x) ? d_bsum[t] : 0;   // NBLK=196 < 256
#pragma unroll
    for (int o = 16; o > 0; o >>= 1) pv += __shfl_xor_sync(0xffffffffu, pv, o);
    if (l == 0) wred[wid] = pv;
    __syncthreads();
    if (t == 0) {
        int acc = 0;
#pragma unroll
        for (int i = 0; i < SCAN_B / 32; i++) acc += wred[i];
        soff = acc;
    }
    __syncthreads();
    if (g < NN) d_rowptr[g] = excl + soff;
    if (g == 0) d_rowptr[NN] = EE;
}

// atomic-free fill: position = rowptr[dst] + rank (rank captured by gemm's hist atomics)
__global__ void fill_csr_kernel(const int* __restrict__ src, const int* __restrict__ dst) {
    int e = blockIdx.x * blockDim.x + threadIdx.x;
    if (e < EE) {
        int d = dst[e];
        int pos = d_rowptr[d] + d_rank[e];
        d_esrc[pos] = src[e];
    }
}

__device__ __forceinline__ float elu_f(float x) { return x > 0.f ? x : expm1f(x); }

// ====================== K7: layer-1 aggregation + fused layer-2 projection ======================
// Plain-exp softmax; warp per dst node; lane l -> features l*8..l*8+7, head = l/4.
// Accumulators packed as f32x2 (fma.rn.f32x2 halves FMA issue count; bit-identical math).
__global__ __launch_bounds__(256) void agg1_kernel(const float* __restrict__ b1,
                                                   const float* __restrict__ W2,
                                                   const float* __restrict__ al2,
                                                   const float* __restrict__ ar2) {
    int w = blockIdx.x * 8 + (threadIdx.x >> 5);
    if (w >= NN) return;
    int l = threadIdx.x & 31;
    int hh = l >> 2;
    int beg = d_rowptr[w], end = d_rowptr[w + 1];

    float o[8];
    const float* bb = b1 + l * 8;

    if (beg == end) {
#pragma unroll
        for (int i = 0; i < 8; i++) o[i] = elu_f(bb[i]);
    } else {
        float er_h = d_er[w * HH + hh];
        float s = 0.f;
        unsigned long long acc01 = 0ull, acc23 = 0ull, acc45 = 0ull, acc67 = 0ull;  // f32x2 {0,0}

#pragma unroll 4
        for (int e = beg; e < end; e++) {
            int si = __ldg(&d_esrc[e]);
            float xv = __ldg(&d_el[si * HH + hh]) + er_h;
            xv = xv > 0.f ? xv : 0.2f * xv;
            float ex = __expf(xv);
            s += ex;
            unsigned long long ex2;
            asm("mov.b64 %0, {%1, %1};" : "=l"(ex2) : "f"(ex));
            uint4 raw = *(const uint4*)(d_zh + (size_t)si * OUTD + l * 8);
            float2 z0 = __half22float2(*(const __half2*)&raw.x);
            float2 z1 = __half22float2(*(const __half2*)&raw.y);
            float2 z2 = __half22float2(*(const __half2*)&raw.z);
            float2 z3 = __half22float2(*(const __half2*)&raw.w);
            unsigned long long p0, p1, p2, p3;
            asm("mov.b64 %0, {%1, %2};" : "=l"(p0) : "f"(z0.x), "f"(z0.y));
            asm("mov.b64 %0, {%1, %2};" : "=l"(p1) : "f"(z1.x), "f"(z1.y));
            asm("mov.b64 %0, {%1, %2};" : "=l"(p2) : "f"(z2.x), "f"(z2.y));
            asm("mov.b64 %0, {%1, %2};" : "=l"(p3) : "f"(z3.x), "f"(z3.y));
            asm("fma.rn.f32x2 %0, %1, %2, %0;" : "+l"(acc01) : "l"(p0), "l"(ex2));
            asm("fma.rn.f32x2 %0, %1, %2, %0;" : "+l"(acc23) : "l"(p1), "l"(ex2));
            asm("fma.rn.f32x2 %0, %1, %2, %0;" : "+l"(acc45) : "l"(p2), "l"(ex2));
            asm("fma.rn.f32x2 %0, %1, %2, %0;" : "+l"(acc67) : "l"(p3), "l"(ex2));
        }
        float acc[8];
        asm("mov.b64 {%0, %1}, %2;" : "=f"(acc[0]), "=f"(acc[1]) : "l"(acc01));
        asm("mov.b64 {%0, %1}, %2;" : "=f"(acc[2]), "=f"(acc[3]) : "l"(acc23));
        asm("mov.b64 {%0, %1}, %2;" : "=f"(acc[4]), "=f"(acc[5]) : "l"(acc45));
        asm("mov.b64 {%0, %1}, %2;" : "=f"(acc[6]), "=f"(acc[7]) : "l"(acc67));
        float inv_s = 1.f / s;
#pragma unroll
        for (int i = 0; i < 8; i++) o[i] = elu_f(fmaf(acc[i], inv_s, bb[i]));
    }

    // ---- fused layer-2 projection: z2 = h @ W2, h held across the warp ----
    float pz0, pz1;
    const float4* W2v = (const float4*)(W2 + l * 16);  // 8 cols x 2 = 16 floats per lane
    float4 w0 = W2v[0], w1 = W2v[1], w2 = W2v[2], w3 = W2v[3];
    pz0 = o[0] * w0.x + o[1] * w0.z + o[2] * w1.x + o[3] * w1.z +
          o[4] * w2.x + o[5] * w2.z + o[6] * w3.x + o[7] * w3.z;
    pz1 = o[0] * w0.y + o[1] * w0.w + o[2] * w1.y + o[3] * w1.w +
          o[4] * w2.y + o[5] * w2.w + o[6] * w3.y + o[7] * w3.w;
#pragma unroll
    for (int sh = 16; sh > 0; sh >>= 1) {
        pz0 += __shfl_xor_sync(0xffffffffu, pz0, sh);
        pz1 += __shfl_xor_sync(0xffffffffu, pz1, sh);
    }
    if (l == 0) {
        float el2v = pz0 * al2[0] + pz1 * al2[1];
        float er2v = pz0 * ar2[0] + pz1 * ar2[1];
        d_rec2[w] = make_float4(pz0, pz1, el2v, er2v);
    }
}

// ====================== K9: layer-2 aggregation (8 lanes per dst, 4 dst/warp) ======================
__global__ __launch_bounds__(256) void agg2_kernel(const float* __restrict__ b2,
                                                   float* __restrict__ out) {
    int l = threadIdx.x & 31;
    int wid = threadIdx.x >> 5;
    int d = blockIdx.x * 32 + wid * 4 + (l >> 3);
    if (d >= NN) return;
    int sub = l & 7;
    int beg = d_rowptr[d], end = d_rowptr[d + 1];
    float erd = d_rec2[d].w;
    float s = 0.f, a0 = 0.f, a1 = 0.f;
    for (int e = beg + sub; e < end; e += 8) {
        int si = __ldg(&d_esrc[e]);
        float4 r = d_rec2[si];
        float xv = r.z + erd;
        xv = xv > 0.f ? xv : 0.2f * xv;
        float ex = __expf(xv);
        s += ex;
        a0 = fmaf(ex, r.x, a0);
        a1 = fmaf(ex, r.y, a1);
    }
#pragma unroll
    for (int o = 4; o > 0; o >>= 1) {
        s  += __shfl_xor_sync(0xffffffffu, s, o);
        a0 += __shfl_xor_sync(0xffffffffu, a0, o);
        a1 += __shfl_xor_sync(0xffffffffu, a1, o);
    }
    if (sub == 0) {
        float o0, o1;
        if (s > 0.f) {
            o0 = a0 / s + b2[0];
            o1 = a1 / s + b2[1];
        } else {
            o0 = b2[0];
            o1 = b2[1];
        }
        out[2 * d + 0] = o0;
        out[2 * d + 1] = o1;
    }
}

// ====================== launch ======================
extern "C" void kernel_launch(void* const* d_in, const int* in_sizes, int n_in,
                              void* d_out, int out_size) {
    const float* x   = (const float*)d_in[0];
    const int*   src = (const int*)d_in[1];
    const int*   dst = (const int*)d_in[2];
    const float* W1  = (const float*)d_in[3];
    const float* al1 = (const float*)d_in[4];
    const float* ar1 = (const float*)d_in[5];
    const float* b1  = (const float*)d_in[6];
    const float* W2  = (const float*)d_in[7];
    const float* al2 = (const float*)d_in[8];
    const float* ar2 = (const float*)d_in[9];
    const float* b2  = (const float*)d_in[10];
    float* out = (float*)d_out;

    dim3 ggrid((NN + GBM - 1) / GBM, OUTD / GBN);   // 391 x 4
    gemm1_mma_kernel<<<ggrid, 256>>>(x, W1, al1, ar1, dst);
    scan_kernel<<<NBLK, SCAN_B>>>();
    fill_csr_kernel<<<(EE + 255) / 256, 256>>>(src, dst);
    agg1_kernel<<<(NN + 7) / 8, 256>>>(b1, W2, al2, ar2);
    agg2_kernel<<<(NN + 31) / 32, 256>>>(b2, out);
}

// round 15
// speedup vs baseline: 1.1316x; 1.0454x over previous
#include <cuda_runtime.h>
#include <cuda_bf16.h>
#include <cuda_fp16.h>
#include <math_constants.h>

#define NN 50000
#define EE 800000
#define INF_DIM 128
#define HH 8
#define FF 32
#define OUTD 256   // HH*FF
#define CC 2

#define SCAN_B 256
#define NBLK ((NN + SCAN_B - 1) / SCAN_B)   // 196

// -------- scratch (static __device__ globals; allocation-free) --------
__device__ __half d_zh[NN * OUTD];     // fp16 projected features (gather payload)
__device__ float  d_el[NN * HH];
__device__ float  d_er[NN * HH];
__device__ int    d_cnt[NN];           // zero on entry every run (BSS init + zero-after-read in scan)
__device__ int    d_rank[EE];          // per-edge rank within its dst (from hist atomics)
__device__ int    d_rowptr[NN + 1];
__device__ int    d_esrc[EE];
__device__ int    d_bsum[NBLK];
__device__ int    d_sbar[2];           // scan grid-barrier: [0]=arrive, [1]=exit (self-resetting)
__device__ float4 d_rec2[NN];          // (z2_0, z2_1, el2, er2) packed per node

// ====================== GEMM1 (tf32 MMA) + fused el/er epilogue + fused histogram ======================
#define GBM 128
#define GBN 64
#define KC 32

__device__ __forceinline__ unsigned f2tf32(float x) {
    unsigned u;
    asm("cvt.rna.tf32.f32 %0, %1;" : "=r"(u) : "f"(x));
    return u;
}

__global__ __launch_bounds__(256) void gemm1_mma_kernel(const float* __restrict__ A,
                                                        const float* __restrict__ B,
                                                        const float* __restrict__ al,
                                                        const float* __restrict__ ar,
                                                        const int* __restrict__ dst) {
    __shared__ float As[GBM][KC + 4];
    __shared__ float Bs[KC][72];

    const int bm = blockIdx.x * GBM;
    const int bn = blockIdx.y * GBN;
    const int tid = threadIdx.x;
    const int wid = tid >> 5;
    const int l = tid & 31;
    const int wm = wid & 3;
    const int wn = wid >> 2;

    // fused histogram + rank assignment: d_cnt is zero at entry (zeroed by scan
    // in the previous replay; BSS zero-init first run). The atomic's return value
    // is this edge's rank within its dst -> enables atomic-free fill.
    {
        const int gstride = gridDim.x * gridDim.y * 256;
        int gt = (blockIdx.y * gridDim.x + blockIdx.x) * 256 + tid;
        for (int e = gt; e < EE; e += gstride) {
            int r = atomicAdd(&d_cnt[dst[e]], 1);
            d_rank[e] = r;
        }
    }

    float c[2][4][4];
#pragma unroll
    for (int mt = 0; mt < 2; mt++)
#pragma unroll
        for (int nt = 0; nt < 4; nt++)
#pragma unroll
            for (int r = 0; r < 4; r++) c[mt][nt][r] = 0.f;

    for (int kc = 0; kc < INF_DIM; kc += KC) {
#pragma unroll
        for (int i = 0; i < 4; i++) {
            int row = (tid >> 3) + i * 32;
            int col = (tid & 7) * 4;
            int grow = bm + row;
            float4 v = make_float4(0.f, 0.f, 0.f, 0.f);
            if (grow < NN) v = *(const float4*)(A + (size_t)grow * INF_DIM + kc + col);
            As[row][col + 0] = __uint_as_float(f2tf32(v.x));
            As[row][col + 1] = __uint_as_float(f2tf32(v.y));
            As[row][col + 2] = __uint_as_float(f2tf32(v.z));
            As[row][col + 3] = __uint_as_float(f2tf32(v.w));
        }
#pragma unroll
        for (int i = 0; i < 2; i++) {
            int k = (tid >> 4) + i * 16;
            int n = (tid & 15) * 4;
            float4 v = *(const float4*)(B + (size_t)(kc + k) * OUTD + bn + n);
            Bs[k][n + 0] = __uint_as_float(f2tf32(v.x));
            Bs[k][n + 1] = __uint_as_float(f2tf32(v.y));
            Bs[k][n + 2] = __uint_as_float(f2tf32(v.z));
            Bs[k][n + 3] = __uint_as_float(f2tf32(v.w));
        }
        __syncthreads();

        const int fr = l >> 2;
        const int fc = l & 3;
#pragma unroll
        for (int ks = 0; ks < KC; ks += 8) {
            unsigned a[2][4], b[4][2];
#pragma unroll
            for (int mt = 0; mt < 2; mt++) {
                int base = wm * 32 + mt * 16;
                a[mt][0] = __float_as_uint(As[base + fr][ks + fc]);
                a[mt][1] = __float_as_uint(As[base + fr + 8][ks + fc]);
                a[mt][2] = __float_as_uint(As[base + fr][ks + fc + 4]);
                a[mt][3] = __float_as_uint(As[base + fr + 8][ks + fc + 4]);
            }
#pragma unroll
            for (int nt = 0; nt < 4; nt++) {
                int coln = wn * 32 + nt * 8 + fr;
                b[nt][0] = __float_as_uint(Bs[ks + fc][coln]);
                b[nt][1] = __float_as_uint(Bs[ks + fc + 4][coln]);
            }
#pragma unroll
            for (int mt = 0; mt < 2; mt++)
#pragma unroll
                for (int nt = 0; nt < 4; nt++) {
                    asm volatile(
                        "mma.sync.aligned.m16n8k8.row.col.f32.tf32.tf32.f32 "
                        "{%0,%1,%2,%3}, {%4,%5,%6,%7}, {%8,%9}, {%0,%1,%2,%3};\n"
                        : "+f"(c[mt][nt][0]), "+f"(c[mt][nt][1]),
                          "+f"(c[mt][nt][2]), "+f"(c[mt][nt][3])
                        : "r"(a[mt][0]), "r"(a[mt][1]), "r"(a[mt][2]), "r"(a[mt][3]),
                          "r"(b[nt][0]), "r"(b[nt][1]));
                }
        }
        __syncthreads();
    }

    const int h = blockIdx.y * 2 + wn;
    const int fr = l >> 2;
    const int fc = l & 3;

    float alv[4][2], arv[4][2];
#pragma unroll
    for (int nt = 0; nt < 4; nt++) {
        int cih = nt * 8 + fc * 2;
        alv[nt][0] = al[h * FF + cih];
        alv[nt][1] = al[h * FF + cih + 1];
        arv[nt][0] = ar[h * FF + cih];
        arv[nt][1] = ar[h * FF + cih + 1];
    }

    float pel[2][2] = {{0.f, 0.f}, {0.f, 0.f}};
    float per[2][2] = {{0.f, 0.f}, {0.f, 0.f}};

#pragma unroll
    for (int mt = 0; mt < 2; mt++) {
        int r0 = bm + wm * 32 + mt * 16 + fr;
        int r1 = r0 + 8;
#pragma unroll
        for (int nt = 0; nt < 4; nt++) {
            float z00 = c[mt][nt][0], z01 = c[mt][nt][1];
            float z10 = c[mt][nt][2], z11 = c[mt][nt][3];
            pel[mt][0] += z00 * alv[nt][0] + z01 * alv[nt][1];
            pel[mt][1] += z10 * alv[nt][0] + z11 * alv[nt][1];
            per[mt][0] += z00 * arv[nt][0] + z01 * arv[nt][1];
            per[mt][1] += z10 * arv[nt][0] + z11 * arv[nt][1];
            int colg = bn + wn * 32 + nt * 8 + fc * 2;
            if (r0 < NN) *(__half2*)(d_zh + (size_t)r0 * OUTD + colg) = __floats2half2_rn(z00, z01);
            if (r1 < NN) *(__half2*)(d_zh + (size_t)r1 * OUTD + colg) = __floats2half2_rn(z10, z11);
        }
    }
#pragma unroll
    for (int o = 1; o < 4; o <<= 1) {
#pragma unroll
        for (int mt = 0; mt < 2; mt++) {
#pragma unroll
            for (int i = 0; i < 2; i++) {
                pel[mt][i] += __shfl_xor_sync(0xffffffffu, pel[mt][i], o);
                per[mt][i] += __shfl_xor_sync(0xffffffffu, per[mt][i], o);
            }
        }
    }
    if (fc == 0) {
#pragma unroll
        for (int mt = 0; mt < 2; mt++) {
#pragma unroll
            for (int i = 0; i < 2; i++) {
                int row = bm + wm * 32 + mt * 16 + fr + i * 8;
                if (row < NN) {
                    d_el[row * HH + h] = pel[mt][i];
                    d_er[row * HH + h] = per[mt][i];
                }
            }
        }
    }
}

// ====================== merged scan: block scan + grid barrier + lookback apply ======================
__device__ __forceinline__ int warp_incl_scan(int v, int l) {
#pragma unroll
    for (int o = 1; o < 32; o <<= 1) {
        int u = __shfl_up_sync(0xffffffffu, v, o);
        if (l >= o) v += u;
    }
    return v;
}

// 196 blocks x 256 threads, 1 barrier. Replay-safe reset: blocks register exit
// AFTER passing the spin; the last exiter resets both counters.
__device__ __forceinline__ void scan_grid_barrier() {
    __syncthreads();
    if (threadIdx.x == 0) {
        __threadfence();
        atomicAdd(&d_sbar[0], 1);
        while (atomicAdd(&d_sbar[0], 0) < NBLK) {}
        __threadfence();
        int ex = atomicAdd(&d_sbar[1], 1);
        if (ex == NBLK - 1) {
            d_sbar[0] = 0;
            d_sbar[1] = 0;
            __threadfence();
        }
    }
    __syncthreads();
}

__global__ __launch_bounds__(SCAN_B) void scan_kernel() {
    const int t = threadIdx.x;
    const int g = blockIdx.x * SCAN_B + t;
    const int l = t & 31;
    const int wid = t >> 5;

    // --- phase 1: block-local exclusive scan; zero-after-read resets d_cnt for next replay ---
    __shared__ int wsum[SCAN_B / 32];
    int v = (g < NN) ? d_cnt[g] : 0;
    if (g < NN) d_cnt[g] = 0;
    int inc = warp_incl_scan(v, l);
    if (l == 31) wsum[wid] = inc;
    __syncthreads();
    if (wid == 0) {
        int wv = (l < SCAN_B / 32) ? wsum[l] : 0;
        wv = warp_incl_scan(wv, l);
        if (l < SCAN_B / 32) wsum[l] = wv;
    }
    __syncthreads();
    int base = (wid == 0) ? 0 : wsum[wid - 1];
    int excl = base + inc - v;
    if (t == SCAN_B - 1) d_bsum[blockIdx.x] = base + inc;

    scan_grid_barrier();

    // --- phase 2: lookback sum of preceding block totals, apply ---
    __shared__ int wred[SCAN_B / 32];
    __shared__ int soff;
    int pv = (t < blockIdx.x) ? d_bsum[t] : 0;   // NBLK=196 < 256
#pragma unroll
    for (int o = 16; o > 0; o >>= 1) pv += __shfl_xor_sync(0xffffffffu, pv, o);
    if (l == 0) wred[wid] = pv;
    __syncthreads();
    if (t == 0) {
        int acc = 0;
#pragma unroll
        for (int i = 0; i < SCAN_B / 32; i++) acc += wred[i];
        soff = acc;
    }
    __syncthreads();
    if (g < NN) d_rowptr[g] = excl + soff;
    if (g == 0) d_rowptr[NN] = EE;
}

// atomic-free fill: position = rowptr[dst] + rank (rank captured by gemm's hist atomics)
__global__ void fill_csr_kernel(const int* __restrict__ src, const int* __restrict__ dst) {
    int e = blockIdx.x * blockDim.x + threadIdx.x;
    if (e < EE) {
        int d = dst[e];
        int pos = d_rowptr[d] + d_rank[e];
        d_esrc[pos] = src[e];
    }
}

__device__ __forceinline__ float elu_f(float x) { return x > 0.f ? x : expm1f(x); }

// ====================== K7: layer-1 aggregation + fused layer-2 projection ======================
// Plain-exp softmax; warp per dst node; lane l -> features l*8..l*8+7, head = l/4.
// Weighted message accumulation in fp16 via HFMA2 directly on the gathered half2s:
// no per-edge half->float conversion, no packing. s stays fp32; accumulators are
// converted to fp32 once per node in the epilogue.
__global__ __launch_bounds__(256) void agg1_kernel(const float* __restrict__ b1,
                                                   const float* __restrict__ W2,
                                                   const float* __restrict__ al2,
                                                   const float* __restrict__ ar2) {
    int w = blockIdx.x * 8 + (threadIdx.x >> 5);
    if (w >= NN) return;
    int l = threadIdx.x & 31;
    int hh = l >> 2;
    int beg = d_rowptr[w], end = d_rowptr[w + 1];

    float o[8];
    const float* bb = b1 + l * 8;

    if (beg == end) {
#pragma unroll
        for (int i = 0; i < 8; i++) o[i] = elu_f(bb[i]);
    } else {
        float er_h = d_er[w * HH + hh];
        float s = 0.f;
        __half2 acch[4];
#pragma unroll
        for (int i = 0; i < 4; i++) acch[i] = __float2half2_rn(0.f);

#pragma unroll 4
        for (int e = beg; e < end; e++) {
            int si = __ldg(&d_esrc[e]);
            float xv = __ldg(&d_el[si * HH + hh]) + er_h;
            xv = xv > 0.f ? xv : 0.2f * xv;
            float ex = __expf(xv);
            s += ex;
            __half2 exh = __float2half2_rn(ex);
            uint4 raw = *(const uint4*)(d_zh + (size_t)si * OUTD + l * 8);
            acch[0] = __hfma2(*(const __half2*)&raw.x, exh, acch[0]);
            acch[1] = __hfma2(*(const __half2*)&raw.y, exh, acch[1]);
            acch[2] = __hfma2(*(const __half2*)&raw.z, exh, acch[2]);
            acch[3] = __hfma2(*(const __half2*)&raw.w, exh, acch[3]);
        }
        float2 f0 = __half22float2(acch[0]);
        float2 f1 = __half22float2(acch[1]);
        float2 f2 = __half22float2(acch[2]);
        float2 f3 = __half22float2(acch[3]);
        float acc[8] = {f0.x, f0.y, f1.x, f1.y, f2.x, f2.y, f3.x, f3.y};
        float inv_s = 1.f / s;
#pragma unroll
        for (int i = 0; i < 8; i++) o[i] = elu_f(fmaf(acc[i], inv_s, bb[i]));
    }

    // ---- fused layer-2 projection: z2 = h @ W2, h held across the warp ----
    float pz0, pz1;
    const float4* W2v = (const float4*)(W2 + l * 16);  // 8 cols x 2 = 16 floats per lane
    float4 w0 = W2v[0], w1 = W2v[1], w2 = W2v[2], w3 = W2v[3];
    pz0 = o[0] * w0.x + o[1] * w0.z + o[2] * w1.x + o[3] * w1.z +
          o[4] * w2.x + o[5] * w2.z + o[6] * w3.x + o[7] * w3.z;
    pz1 = o[0] * w0.y + o[1] * w0.w + o[2] * w1.y + o[3] * w1.w +
          o[4] * w2.y + o[5] * w2.w + o[6] * w3.y + o[7] * w3.w;
#pragma unroll
    for (int sh = 16; sh > 0; sh >>= 1) {
        pz0 += __shfl_xor_sync(0xffffffffu, pz0, sh);
        pz1 += __shfl_xor_sync(0xffffffffu, pz1, sh);
    }
    if (l == 0) {
        float el2v = pz0 * al2[0] + pz1 * al2[1];
        float er2v = pz0 * ar2[0] + pz1 * ar2[1];
        d_rec2[w] = make_float4(pz0, pz1, el2v, er2v);
    }
}

// ====================== K9: layer-2 aggregation (8 lanes per dst, 4 dst/warp) ======================
__global__ __launch_bounds__(256) void agg2_kernel(const float* __restrict__ b2,
                                                   float* __restrict__ out) {
    int l = threadIdx.x & 31;
    int wid = threadIdx.x >> 5;
    int d = blockIdx.x * 32 + wid * 4 + (l >> 3);
    if (d >= NN) return;
    int sub = l & 7;
    int beg = d_rowptr[d], end = d_rowptr[d + 1];
    float erd = d_rec2[d].w;
    float s = 0.f, a0 = 0.f, a1 = 0.f;
    for (int e = beg + sub; e < end; e += 8) {
        int si = __ldg(&d_esrc[e]);
        float4 r = d_rec2[si];
        float xv = r.z + erd;
        xv = xv > 0.f ? xv : 0.2f * xv;
        float ex = __expf(xv);
        s += ex;
        a0 = fmaf(ex, r.x, a0);
        a1 = fmaf(ex, r.y, a1);
    }
#pragma unroll
    for (int o = 4; o > 0; o >>= 1) {
        s  += __shfl_xor_sync(0xffffffffu, s, o);
        a0 += __shfl_xor_sync(0xffffffffu, a0, o);
        a1 += __shfl_xor_sync(0xffffffffu, a1, o);
    }
    if (sub == 0) {
        float o0, o1;
        if (s > 0.f) {
            o0 = a0 / s + b2[0];
            o1 = a1 / s + b2[1];
        } else {
            o0 = b2[0];
            o1 = b2[1];
        }
        out[2 * d + 0] = o0;
        out[2 * d + 1] = o1;
    }
}

// ====================== launch ======================
extern "C" void kernel_launch(void* const* d_in, const int* in_sizes, int n_in,
                              void* d_out, int out_size) {
    const float* x   = (const float*)d_in[0];
    const int*   src = (const int*)d_in[1];
    const int*   dst = (const int*)d_in[2];
    const float* W1  = (const float*)d_in[3];
    const float* al1 = (const float*)d_in[4];
    const float* ar1 = (const float*)d_in[5];
    const float* b1  = (const float*)d_in[6];
    const float* W2  = (const float*)d_in[7];
    const float* al2 = (const float*)d_in[8];
    const float* ar2 = (const float*)d_in[9];
    const float* b2  = (const float*)d_in[10];
    float* out = (float*)d_out;

    dim3 ggrid((NN + GBM - 1) / GBM, OUTD / GBN);   // 391 x 4
    gemm1_mma_kernel<<<ggrid, 256>>>(x, W1, al1, ar1, dst);
    scan_kernel<<<NBLK, SCAN_B>>>();
    fill_csr_kernel<<<(EE + 255) / 256, 256>>>(src, dst);
    agg1_kernel<<<(NN + 7) / 8, 256>>>(b1, W2, al2, ar2);
    agg2_kernel<<<(NN + 31) / 32, 256>>>(b2, out);
}